// round 1
// baseline (speedup 1.0000x reference)
#include <cuda_runtime.h>

// Output layout (floats): concatenated mips L0(2048)..L7(16), each [6,H,W,3] row-major.
static const size_t OFF1 = 75497472ull;   // after L0
static const size_t OFF2 = 94371840ull;   // after L1
static const size_t OFFS[8] = {
    0ull, 75497472ull, 94371840ull, 99090432ull,
    100270080ull, 100564992ull, 100638720ull, 100657152ull
};

// Kernel A: fused {copy base -> L0 out} + {2x2 pool -> L1} + {4x4 pool -> L2}.
// One thread per L2 pixel (all 3 channels): reads a 4x4 base block (12 float4),
// writes the copy (12 float4), 2x2 L1 pixels (6 float2), 1 L2 pixel (3 floats).
__global__ void __launch_bounds__(256) fuse012_kernel(const float* __restrict__ in,
                                                      float* __restrict__ out) {
    const int tid = blockIdx.x * 256 + threadIdx.x;     // exactly 6*512*512 threads
    const int x2 = tid & 511;
    const int y2 = (tid >> 9) & 511;
    const int f  = tid >> 18;

    // Base 4x4 block origin, row stride = 2048*3 = 6144 floats.
    const size_t row0 = ((size_t)(f * 2048 + y2 * 4) * 2048 + (size_t)x2 * 4) * 3;

    float a[4][12];
    #pragma unroll
    for (int r = 0; r < 4; r++) {
        const float4* p = reinterpret_cast<const float4*>(in + row0 + (size_t)r * 6144);
        float4 u0 = p[0];
        float4 u1 = p[1];
        float4 u2 = p[2];
        float4* q = reinterpret_cast<float4*>(out + row0 + (size_t)r * 6144);
        q[0] = u0; q[1] = u1; q[2] = u2;
        a[r][0] = u0.x; a[r][1]  = u0.y; a[r][2]  = u0.z; a[r][3]  = u0.w;
        a[r][4] = u1.x; a[r][5]  = u1.y; a[r][6]  = u1.z; a[r][7]  = u1.w;
        a[r][8] = u2.x; a[r][9]  = u2.y; a[r][10] = u2.z; a[r][11] = u2.w;
    }

    // L1: 2x2 pixels, 3 channels each. Row floats are [p0.rgb p1.rgb p2.rgb p3.rgb].
    float m[2][6];
    #pragma unroll
    for (int r = 0; r < 2; r++)
        #pragma unroll
        for (int s = 0; s < 2; s++)
            #pragma unroll
            for (int c = 0; c < 3; c++)
                m[r][s * 3 + c] = 0.25f * (a[2 * r][6 * s + c] + a[2 * r][6 * s + c + 3] +
                                           a[2 * r + 1][6 * s + c] + a[2 * r + 1][6 * s + c + 3]);

    #pragma unroll
    for (int r = 0; r < 2; r++) {
        const size_t o1 = OFF1 + ((size_t)(f * 1024 + (y2 * 2 + r)) * 1024 + (size_t)x2 * 2) * 3;
        float2* q = reinterpret_cast<float2*>(out + o1);     // 24-byte offset -> 8B aligned
        q[0] = make_float2(m[r][0], m[r][1]);
        q[1] = make_float2(m[r][2], m[r][3]);
        q[2] = make_float2(m[r][4], m[r][5]);
    }

    // L2: average the 4 L1 pixels.
    const size_t o2 = OFF2 + ((size_t)(f * 512 + y2) * 512 + x2) * 3;
    #pragma unroll
    for (int c = 0; c < 3; c++)
        out[o2 + c] = 0.25f * (m[0][c] + m[0][c + 3] + m[1][c] + m[1][c + 3]);
}

// Kernel B: generic 2x2 avg pool, one thread per output pixel (3 channels).
// W = output width (power of two).
__global__ void pool_kernel(const float* __restrict__ in, float* __restrict__ out,
                            int W, int n) {
    const int tid = blockIdx.x * blockDim.x + threadIdx.x;
    if (tid >= n) return;
    const int x = tid & (W - 1);
    const int t = tid / W;
    const int y = t & (W - 1);
    const int f = t / W;
    const int Wi = W * 2;

    const size_t ib = ((size_t)(f * Wi + 2 * y) * Wi + (size_t)2 * x) * 3;
    const float2* p0 = reinterpret_cast<const float2*>(in + ib);                   // 8B aligned
    const float2* p1 = reinterpret_cast<const float2*>(in + ib + (size_t)Wi * 3);
    const float2 a0 = p0[0], a1 = p0[1], a2 = p0[2];
    const float2 b0 = p1[0], b1 = p1[1], b2 = p1[2];

    // row floats: [c0 c1 c2 | c0' c1' c2'] for pixels x*2 and x*2+1
    const float r0 = a0.x + a1.y;
    const float r1 = a0.y + a2.x;
    const float r2 = a1.x + a2.y;
    const float s0 = b0.x + b1.y;
    const float s1 = b0.y + b2.x;
    const float s2 = b1.x + b2.y;

    const size_t ob = ((size_t)(f * W + y) * W + x) * 3;
    out[ob + 0] = 0.25f * (r0 + s0);
    out[ob + 1] = 0.25f * (r1 + s1);
    out[ob + 2] = 0.25f * (r2 + s2);
}

extern "C" void kernel_launch(void* const* d_in, const int* in_sizes, int n_in,
                              void* d_out, int out_size) {
    const float* base = (const float*)d_in[0];
    float* out = (float*)d_out;

    // L0 copy + L1 + L2, fused (reads base exactly once).
    fuse012_kernel<<<6144, 256>>>(base, out);

    // L3..L7 chained pools (all data L2-cache resident).
    int W = 256;
    for (int lvl = 3; lvl <= 7; lvl++) {
        const int n = 6 * W * W;
        pool_kernel<<<(n + 255) / 256, 256>>>(out + OFFS[lvl - 1], out + OFFS[lvl], W, n);
        W >>= 1;
    }
}

// round 2
// speedup vs baseline: 1.6283x; 1.6283x over previous
#include <cuda_runtime.h>

// Output layout (floats): concatenated mips L0(2048)..L7(16), each [6,H,W,3] row-major.
#define OFF1 75497472ull
#define OFF2 94371840ull
#define OFF3 99090432ull
#define OFF4 100270080ull
#define OFF5 100564992ull
#define OFF6 100638720ull
#define OFF7 100657152ull

// ---------------------------------------------------------------------------
// Kernel A: L0 copy + L1 + L2 (register) + L3 + L4 (smem block reductions).
// Block = 16x16 threads = 16x16 L2 pixels = 64x64 base pixels.
// Grid = (32, 32, 6).
// All global streams except L4 are single-use -> .cs (evict-first) hints.
// ---------------------------------------------------------------------------
__global__ void __launch_bounds__(256) fuseA_kernel(const float* __restrict__ in,
                                                    float* __restrict__ out) {
    const int tx = threadIdx.x, ty = threadIdx.y;
    const int f = blockIdx.z;
    const int x2 = blockIdx.x * 16 + tx;          // L2 coords (512-wide)
    const int y2 = blockIdx.y * 16 + ty;

    __shared__ float s2[16 * 16 * 3];
    __shared__ float s3[8 * 8 * 3];

    // ---- read 4x4 base block, write L0 copy ----
    const size_t row0 = ((size_t)(f * 2048 + y2 * 4) * 2048 + (size_t)x2 * 4) * 3;
    float a[4][12];
    #pragma unroll
    for (int r = 0; r < 4; r++) {
        const float4* p = reinterpret_cast<const float4*>(in + row0 + (size_t)r * 6144);
        float4 u0 = __ldcs(p + 0);
        float4 u1 = __ldcs(p + 1);
        float4 u2 = __ldcs(p + 2);
        float4* q = reinterpret_cast<float4*>(out + row0 + (size_t)r * 6144);
        __stcs(q + 0, u0);
        __stcs(q + 1, u1);
        __stcs(q + 2, u2);
        a[r][0] = u0.x; a[r][1]  = u0.y; a[r][2]  = u0.z; a[r][3]  = u0.w;
        a[r][4] = u1.x; a[r][5]  = u1.y; a[r][6]  = u1.z; a[r][7]  = u1.w;
        a[r][8] = u2.x; a[r][9]  = u2.y; a[r][10] = u2.z; a[r][11] = u2.w;
    }

    // ---- L1: 2x2 output pixels ----
    float m[2][6];
    #pragma unroll
    for (int r = 0; r < 2; r++)
        #pragma unroll
        for (int s = 0; s < 2; s++)
            #pragma unroll
            for (int c = 0; c < 3; c++)
                m[r][s * 3 + c] = 0.25f * (a[2 * r][6 * s + c] + a[2 * r][6 * s + c + 3] +
                                           a[2 * r + 1][6 * s + c] + a[2 * r + 1][6 * s + c + 3]);
    #pragma unroll
    for (int r = 0; r < 2; r++) {
        const size_t o1 = OFF1 + ((size_t)(f * 1024 + (y2 * 2 + r)) * 1024 + (size_t)x2 * 2) * 3;
        float2* q = reinterpret_cast<float2*>(out + o1);   // 24B-multiple offset -> 8B aligned
        __stcs(q + 0, make_float2(m[r][0], m[r][1]));
        __stcs(q + 1, make_float2(m[r][2], m[r][3]));
        __stcs(q + 2, make_float2(m[r][4], m[r][5]));
    }

    // ---- L2: 1 pixel, to global (.cs, never re-read) + smem ----
    const size_t o2 = OFF2 + ((size_t)(f * 512 + y2) * 512 + x2) * 3;
    #pragma unroll
    for (int c = 0; c < 3; c++) {
        const float v = 0.25f * (m[0][c] + m[0][c + 3] + m[1][c] + m[1][c + 3]);
        __stcs(out + o2 + c, v);
        s2[(ty * 16 + tx) * 3 + c] = v;
    }
    __syncthreads();

    // ---- L3: 8x8 per block (face 256) ----
    const int tid = ty * 16 + tx;
    if (tid < 64) {
        const int x3 = tid & 7, y3 = tid >> 3;
        const size_t o3 = OFF3 +
            ((size_t)(f * 256 + blockIdx.y * 8 + y3) * 256 + (size_t)(blockIdx.x * 8 + x3)) * 3;
        #pragma unroll
        for (int c = 0; c < 3; c++) {
            const float v = 0.25f * (s2[((2 * y3)     * 16 + 2 * x3)     * 3 + c] +
                                     s2[((2 * y3)     * 16 + 2 * x3 + 1) * 3 + c] +
                                     s2[((2 * y3 + 1) * 16 + 2 * x3)     * 3 + c] +
                                     s2[((2 * y3 + 1) * 16 + 2 * x3 + 1) * 3 + c]);
            __stcs(out + o3 + c, v);
            s3[(y3 * 8 + x3) * 3 + c] = v;
        }
    }
    __syncthreads();

    // ---- L4: 4x4 per block (face 128); re-read by kernel B -> normal store ----
    if (tid < 16) {
        const int x4 = tid & 3, y4 = tid >> 2;
        const size_t o4 = OFF4 +
            ((size_t)(f * 128 + blockIdx.y * 4 + y4) * 128 + (size_t)(blockIdx.x * 4 + x4)) * 3;
        #pragma unroll
        for (int c = 0; c < 3; c++)
            out[o4 + c] = 0.25f * (s3[((2 * y4)     * 8 + 2 * x4)     * 3 + c] +
                                   s3[((2 * y4)     * 8 + 2 * x4 + 1) * 3 + c] +
                                   s3[((2 * y4 + 1) * 8 + 2 * x4)     * 3 + c] +
                                   s3[((2 * y4 + 1) * 8 + 2 * x4 + 1) * 3 + c]);
    }
}

// ---------------------------------------------------------------------------
// Kernel B: L5 + L6 + L7 from L4. Block = 16x16 threads covering 32x32 L4
// pixels -> 16x16 L5, 8x8 L6, 4x4 L7. Grid = (4, 4, 6). All L2-resident.
// ---------------------------------------------------------------------------
__global__ void __launch_bounds__(256) fuseB_kernel(float* __restrict__ out) {
    const float* l4 = out + OFF4;                  // face 128
    const int tx = threadIdx.x, ty = threadIdx.y;
    const int f = blockIdx.z;
    const int x5 = blockIdx.x * 16 + tx;           // L5 coords (64-wide)
    const int y5 = blockIdx.y * 16 + ty;

    __shared__ float s5[16 * 16 * 3];
    __shared__ float s6[8 * 8 * 3];

    // read 2x2 L4 pixels (6 floats per row, 8B aligned)
    const size_t ib = ((size_t)(f * 128 + 2 * y5) * 128 + (size_t)2 * x5) * 3;
    const float2* p0 = reinterpret_cast<const float2*>(l4 + ib);
    const float2* p1 = reinterpret_cast<const float2*>(l4 + ib + 128 * 3);
    const float2 a0 = p0[0], a1 = p0[1], a2 = p0[2];
    const float2 b0 = p1[0], b1 = p1[1], b2 = p1[2];

    float v5[3];
    v5[0] = 0.25f * ((a0.x + a1.y) + (b0.x + b1.y));
    v5[1] = 0.25f * ((a0.y + a2.x) + (b0.y + b2.x));
    v5[2] = 0.25f * ((a1.x + a2.y) + (b1.x + b2.y));

    const size_t o5 = OFF5 + ((size_t)(f * 64 + y5) * 64 + x5) * 3;
    #pragma unroll
    for (int c = 0; c < 3; c++) {
        out[o5 + c] = v5[c];
        s5[(ty * 16 + tx) * 3 + c] = v5[c];
    }
    __syncthreads();

    const int tid = ty * 16 + tx;
    if (tid < 64) {
        const int x6 = tid & 7, y6 = tid >> 3;
        const size_t o6 = OFF6 +
            ((size_t)(f * 32 + blockIdx.y * 8 + y6) * 32 + (size_t)(blockIdx.x * 8 + x6)) * 3;
        #pragma unroll
        for (int c = 0; c < 3; c++) {
            const float v = 0.25f * (s5[((2 * y6)     * 16 + 2 * x6)     * 3 + c] +
                                     s5[((2 * y6)     * 16 + 2 * x6 + 1) * 3 + c] +
                                     s5[((2 * y6 + 1) * 16 + 2 * x6)     * 3 + c] +
                                     s5[((2 * y6 + 1) * 16 + 2 * x6 + 1) * 3 + c]);
            out[o6 + c] = v;
            s6[(y6 * 8 + x6) * 3 + c] = v;
        }
    }
    __syncthreads();

    if (tid < 16) {
        const int x7 = tid & 3, y7 = tid >> 2;
        const size_t o7 = OFF7 +
            ((size_t)(f * 16 + blockIdx.y * 4 + y7) * 16 + (size_t)(blockIdx.x * 4 + x7)) * 3;
        #pragma unroll
        for (int c = 0; c < 3; c++)
            out[o7 + c] = 0.25f * (s6[((2 * y7)     * 8 + 2 * x7)     * 3 + c] +
                                   s6[((2 * y7)     * 8 + 2 * x7 + 1) * 3 + c] +
                                   s6[((2 * y7 + 1) * 8 + 2 * x7)     * 3 + c] +
                                   s6[((2 * y7 + 1) * 8 + 2 * x7 + 1) * 3 + c]);
    }
}

extern "C" void kernel_launch(void* const* d_in, const int* in_sizes, int n_in,
                              void* d_out, int out_size) {
    const float* base = (const float*)d_in[0];
    float* out = (float*)d_out;

    fuseA_kernel<<<dim3(32, 32, 6), dim3(16, 16)>>>(base, out);   // L0..L4
    fuseB_kernel<<<dim3(4, 4, 6),   dim3(16, 16)>>>(out);          // L5..L7
}